// round 2
// baseline (speedup 1.0000x reference)
#include <cuda_runtime.h>
#include <cuda_bf16.h>
#include <cstdint>

#define BDIM   1024
#define BATCH  32
#define SEQ    2048
#define MROWS  (BATCH * SEQ)

#define BM 128
#define BN 128
#define BK 32
#define STRIDE 36                 // floats per smem row (pad: conflict-free frags)
#define KTILES (BDIM / BK)        // 32
#define NTILES (BDIM / BN)        // 8
#define SMEM_FLOATS (4 * 128 * STRIDE + 128)
#define SMEM_BYTES  (SMEM_FLOATS * 4)

__device__ float g_logits[MROWS];

__device__ __forceinline__ uint32_t cvt_tf32(float x) {
    uint32_t r;
    asm("cvt.rna.tf32.f32 %0, %1;" : "=r"(r) : "f"(x));
    return r;
}

__device__ __forceinline__ float fast_tanh(float x) {
    // tanh(x) = 1 - 2/(exp(2x)+1). ex2.approx + rcp-based fast divide: ~1e-6 err.
    float e = __expf(2.0f * x);
    return 1.0f - __fdividef(2.0f, e + 1.0f);
}

__device__ __forceinline__ uint32_t smem_u32(const void* p) {
    return (uint32_t)__cvta_generic_to_shared(p);
}

__device__ __forceinline__ void cp_async16(uint32_t saddr, const void* gaddr) {
    asm volatile("cp.async.cg.shared.global [%0], [%1], 16;\n" :: "r"(saddr), "l"(gaddr));
}

// ---------------------------------------------------------------------------
// Kernel A: logits[m] = sum_e v[e] * tanh( sum_d X[m,d] * W[e,d] )
// tf32 mma.sync GEMM, fused tanh + v-dot epilogue. One CTA per 128-row M tile.
// ---------------------------------------------------------------------------
__global__ __launch_bounds__(256, 2)
void logits_kernel(const float* __restrict__ X, const float* __restrict__ W,
                   const float* __restrict__ v) {
    extern __shared__ float smem[];
    float* As0 = smem;
    float* Bs0 = smem + 128 * STRIDE;
    float* As1 = smem + 2 * 128 * STRIDE;
    float* Bs1 = smem + 3 * 128 * STRIDE;
    float* rowsum = smem + 4 * 128 * STRIDE;

    const int tid  = threadIdx.x;
    const int warp = tid >> 5;
    const int lane = tid & 31;
    const int wm = warp >> 1;          // 0..3  (32-row groups)
    const int wn = warp & 1;           // 0..1  (64-col groups)
    const int l4 = lane & 3;
    const int lg = lane >> 2;

    const int m0 = blockIdx.x * BM;

    if (tid < 128) rowsum[tid] = 0.0f;

    // tile-loader indexing: each thread loads 4 float4 per tile
    const int lr = tid >> 3;           // 0..31
    const int lc = (tid & 7) * 4;      // float col offset (16B aligned)

    float part[4] = {0.f, 0.f, 0.f, 0.f};

    for (int nt = 0; nt < NTILES; ++nt) {
        const float* Bbase = W + (size_t)(nt * BN) * BDIM;

        float acc[2][8][4];
        #pragma unroll
        for (int i = 0; i < 2; ++i)
            #pragma unroll
            for (int j = 0; j < 8; ++j)
                #pragma unroll
                for (int q = 0; q < 4; ++q) acc[i][j][q] = 0.0f;

        // prefetch k-tile 0 into buffer 0
        #pragma unroll
        for (int i = 0; i < 4; ++i) {
            int r = lr + 32 * i;
            cp_async16(smem_u32(&As0[r * STRIDE + lc]),
                       X + (size_t)(m0 + r) * BDIM + lc);
            cp_async16(smem_u32(&Bs0[r * STRIDE + lc]),
                       Bbase + (size_t)r * BDIM + lc);
        }
        asm volatile("cp.async.commit_group;\n");

        for (int kt = 0; kt < KTILES; ++kt) {
            asm volatile("cp.async.wait_group 0;\n");
            __syncthreads();

            const float* A = (kt & 1) ? As1 : As0;
            const float* B = (kt & 1) ? Bs1 : Bs0;

            if (kt + 1 < KTILES) {
                float* An = (kt & 1) ? As0 : As1;
                float* Bn = (kt & 1) ? Bs0 : Bs1;
                const int kof = (kt + 1) * BK;
                #pragma unroll
                for (int i = 0; i < 4; ++i) {
                    int r = lr + 32 * i;
                    cp_async16(smem_u32(&An[r * STRIDE + lc]),
                               X + (size_t)(m0 + r) * BDIM + kof + lc);
                    cp_async16(smem_u32(&Bn[r * STRIDE + lc]),
                               Bbase + (size_t)r * BDIM + kof + lc);
                }
                asm volatile("cp.async.commit_group;\n");
            }

            #pragma unroll
            for (int kk = 0; kk < 4; ++kk) {
                const int kc = kk * 8 + l4;
                uint32_t bf[8][2];
                #pragma unroll
                for (int j = 0; j < 8; ++j) {
                    int n = wn * 64 + j * 8 + lg;
                    bf[j][0] = cvt_tf32(B[n * STRIDE + kc]);
                    bf[j][1] = cvt_tf32(B[n * STRIDE + kc + 4]);
                }
                #pragma unroll
                for (int mi = 0; mi < 2; ++mi) {
                    int r = wm * 32 + mi * 16 + lg;
                    uint32_t a0 = cvt_tf32(A[r * STRIDE + kc]);
                    uint32_t a1 = cvt_tf32(A[(r + 8) * STRIDE + kc]);
                    uint32_t a2 = cvt_tf32(A[r * STRIDE + kc + 4]);
                    uint32_t a3 = cvt_tf32(A[(r + 8) * STRIDE + kc + 4]);
                    #pragma unroll
                    for (int j = 0; j < 8; ++j) {
                        asm volatile(
                            "mma.sync.aligned.m16n8k8.row.col.f32.tf32.tf32.f32 "
                            "{%0,%1,%2,%3}, {%4,%5,%6,%7}, {%8,%9}, {%0,%1,%2,%3};\n"
                            : "+f"(acc[mi][j][0]), "+f"(acc[mi][j][1]),
                              "+f"(acc[mi][j][2]), "+f"(acc[mi][j][3])
                            : "r"(a0), "r"(a1), "r"(a2), "r"(a3),
                              "r"(bf[j][0]), "r"(bf[j][1]));
                    }
                }
            }
            __syncthreads();
        }

        // fused epilogue for this n-tile: tanh then dot with v, per-row partials
        #pragma unroll
        for (int mi = 0; mi < 2; ++mi) {
            #pragma unroll
            for (int j = 0; j < 8; ++j) {
                int c = nt * BN + wn * 64 + j * 8 + l4 * 2;
                float v0 = __ldg(&v[c]);
                float v1 = __ldg(&v[c + 1]);
                part[mi * 2 + 0] += v0 * fast_tanh(acc[mi][j][0])
                                  + v1 * fast_tanh(acc[mi][j][1]);
                part[mi * 2 + 1] += v0 * fast_tanh(acc[mi][j][2])
                                  + v1 * fast_tanh(acc[mi][j][3]);
            }
        }
    }

    // reduce the 4 lanes that share each row (same lg, l4 = 0..3)
    #pragma unroll
    for (int p = 0; p < 4; ++p) {
        part[p] += __shfl_xor_sync(0xffffffffu, part[p], 1);
        part[p] += __shfl_xor_sync(0xffffffffu, part[p], 2);
    }
    if (l4 == 0) {
        int rbase = wm * 32 + lg;
        atomicAdd(&rowsum[rbase + 0],  part[0]);
        atomicAdd(&rowsum[rbase + 8],  part[1]);
        atomicAdd(&rowsum[rbase + 16], part[2]);
        atomicAdd(&rowsum[rbase + 24], part[3]);
    }
    __syncthreads();
    if (tid < 128) g_logits[m0 + tid] = rowsum[tid];
}

// ---------------------------------------------------------------------------
// Kernel B: softmax over S=2048 per batch. Also zero-fills the weighted-
// context region of d_out (bias b omitted: softmax is shift-invariant).
// ---------------------------------------------------------------------------
__global__ void softmax_kernel(float* __restrict__ out) {
    __shared__ float red[8];
    const int b = blockIdx.x;
    const int tid = threadIdx.x;
    const int warp = tid >> 5, lane = tid & 31;
    const float* lp = g_logits + b * SEQ;

    float vals[8];
    float m = -1e30f;
    #pragma unroll
    for (int i = 0; i < 8; ++i) {
        vals[i] = lp[i * 256 + tid];
        m = fmaxf(m, vals[i]);
    }
    #pragma unroll
    for (int o = 16; o > 0; o >>= 1) m = fmaxf(m, __shfl_xor_sync(~0u, m, o));
    if (lane == 0) red[warp] = m;
    __syncthreads();
    float bm = red[0];
    #pragma unroll
    for (int w = 1; w < 8; ++w) bm = fmaxf(bm, red[w]);
    __syncthreads();

    float s = 0.0f;
    #pragma unroll
    for (int i = 0; i < 8; ++i) {
        vals[i] = __expf(vals[i] - bm);
        s += vals[i];
    }
    #pragma unroll
    for (int o = 16; o > 0; o >>= 1) s += __shfl_xor_sync(~0u, s, o);
    if (lane == 0) red[warp] = s;
    __syncthreads();
    float ts = 0.0f;
    #pragma unroll
    for (int w = 0; w < 8; ++w) ts += red[w];

    float inv = 1.0f / ts;
    #pragma unroll
    for (int i = 0; i < 8; ++i)
        out[BATCH * BDIM + b * SEQ + i * 256 + tid] = vals[i] * inv;

    // zero weighted-context region (accumulated atomically by kernel C)
    for (int d = tid; d < BDIM; d += 256) out[b * BDIM + d] = 0.0f;
}

// ---------------------------------------------------------------------------
// Kernel C: weighted_context[b,d] = sum_s attn[b,s] * X[b,s,d]
// grid (4 d-chunks, 4 s-chunks, 32 batches); memory bound.
// ---------------------------------------------------------------------------
__global__ void weighted_kernel(const float* __restrict__ X, float* __restrict__ out) {
    const int d  = blockIdx.x * 256 + threadIdx.x;
    const int b  = blockIdx.z;
    const int s0 = blockIdx.y * 512;
    const float* attn = out + BATCH * BDIM + b * SEQ;
    const float* xb = X + ((size_t)b * SEQ + s0) * BDIM + d;

    float a0 = 0.f, a1 = 0.f, a2 = 0.f, a3 = 0.f;
    for (int s = 0; s < 512; s += 4) {
        a0 += attn[s0 + s + 0] * xb[(size_t)(s + 0) * BDIM];
        a1 += attn[s0 + s + 1] * xb[(size_t)(s + 1) * BDIM];
        a2 += attn[s0 + s + 2] * xb[(size_t)(s + 2) * BDIM];
        a3 += attn[s0 + s + 3] * xb[(size_t)(s + 3) * BDIM];
    }
    atomicAdd(&out[b * BDIM + d], (a0 + a1) + (a2 + a3));
}

// ---------------------------------------------------------------------------
extern "C" void kernel_launch(void* const* d_in, const int* in_sizes, int n_in,
                              void* d_out, int out_size) {
    const float* X = (const float*)d_in[0];   // context [32,2048,1024]
    const float* W = (const float*)d_in[1];   // [1024,1024]
    const float* v = (const float*)d_in[2];   // [1024]
    // d_in[3] = b: irrelevant (softmax shift invariance)
    float* out = (float*)d_out;               // [wc 32*1024 | attn 32*2048]

    cudaFuncSetAttribute(logits_kernel,
                         cudaFuncAttributeMaxDynamicSharedMemorySize, SMEM_BYTES);

    logits_kernel<<<MROWS / BM, 256, SMEM_BYTES>>>(X, W, v);
    softmax_kernel<<<BATCH, 256>>>(out);
    weighted_kernel<<<dim3(4, 4, BATCH), 256>>>(X, out);
}

// round 4
// speedup vs baseline: 1.0939x; 1.0939x over previous
#include <cuda_runtime.h>
#include <cuda_bf16.h>
#include <cstdint>

#define BDIM   1024
#define BATCH  32
#define SEQ    2048
#define MROWS  (BATCH * SEQ)

#define BM 128
#define BN 128
#define BK 32
#define STRIDE 36                 // floats per smem row (pad: conflict-free frags)
#define KTILES (BDIM / BK)        // 32
#define NTILES (BDIM / BN)        // 8
#define SMEM_FLOATS (4 * 128 * STRIDE + 128)
#define SMEM_BYTES  (SMEM_FLOATS * 4)

__device__ float g_logits[MROWS];

__device__ __forceinline__ uint32_t cvt_tf32(float x) {
    uint32_t r;
    asm("cvt.rna.tf32.f32 %0, %1;" : "=r"(r) : "f"(x));
    return r;
}

__device__ __forceinline__ float fast_tanh(float x) {
    // tanh(x) = 1 - 2/(exp(2x)+1). ex2.approx + fast divide: ~1e-6 err.
    float e = __expf(2.0f * x);
    return 1.0f - __fdividef(2.0f, e + 1.0f);
}

__device__ __forceinline__ uint32_t smem_u32(const void* p) {
    return (uint32_t)__cvta_generic_to_shared(p);
}

__device__ __forceinline__ void cp_async16(uint32_t saddr, const void* gaddr) {
    asm volatile("cp.async.cg.shared.global [%0], [%1], 16;\n" :: "r"(saddr), "l"(gaddr));
}

// ---------------------------------------------------------------------------
// Kernel A: logits[m] = sum_e v[e] * tanh( sum_d X[m,d] * W[e,d] )
// tf32 mma.sync GEMM. B fragments fed as RAW fp32 bits (HW truncates to tf32,
// zero ALU cost); A fragments rna-rounded (4 cvt per 16 MMA).
// ---------------------------------------------------------------------------
__global__ __launch_bounds__(256, 2)
void logits_kernel(const float* __restrict__ X, const float* __restrict__ W,
                   const float* __restrict__ v) {
    extern __shared__ float smem[];
    float* As0 = smem;
    float* Bs0 = smem + 128 * STRIDE;
    float* As1 = smem + 2 * 128 * STRIDE;
    float* Bs1 = smem + 3 * 128 * STRIDE;
    float* rowsum = smem + 4 * 128 * STRIDE;

    const int tid  = threadIdx.x;
    const int warp = tid >> 5;
    const int lane = tid & 31;
    const int wm = warp >> 1;          // 0..3  (32-row groups)
    const int wn = warp & 1;           // 0..1  (64-col groups)
    const int l4 = lane & 3;
    const int lg = lane >> 2;

    const int m0 = blockIdx.x * BM;

    if (tid < 128) rowsum[tid] = 0.0f;

    const int lr = tid >> 3;           // 0..31
    const int lc = (tid & 7) * 4;      // float col offset (16B aligned)

    float part[4] = {0.f, 0.f, 0.f, 0.f};

    for (int nt = 0; nt < NTILES; ++nt) {
        const float* Bbase = W + (size_t)(nt * BN) * BDIM;

        float acc[2][8][4];
        #pragma unroll
        for (int i = 0; i < 2; ++i)
            #pragma unroll
            for (int j = 0; j < 8; ++j)
                #pragma unroll
                for (int q = 0; q < 4; ++q) acc[i][j][q] = 0.0f;

        // prefetch k-tile 0 into buffer 0
        #pragma unroll
        for (int i = 0; i < 4; ++i) {
            int r = lr + 32 * i;
            cp_async16(smem_u32(&As0[r * STRIDE + lc]),
                       X + (size_t)(m0 + r) * BDIM + lc);
            cp_async16(smem_u32(&Bs0[r * STRIDE + lc]),
                       Bbase + (size_t)r * BDIM + lc);
        }
        asm volatile("cp.async.commit_group;\n");

        for (int kt = 0; kt < KTILES; ++kt) {
            asm volatile("cp.async.wait_group 0;\n");
            __syncthreads();

            const float* A = (kt & 1) ? As1 : As0;
            const float* B = (kt & 1) ? Bs1 : Bs0;

            if (kt + 1 < KTILES) {
                float* An = (kt & 1) ? As0 : As1;
                float* Bn = (kt & 1) ? Bs0 : Bs1;
                const int kof = (kt + 1) * BK;
                #pragma unroll
                for (int i = 0; i < 4; ++i) {
                    int r = lr + 32 * i;
                    cp_async16(smem_u32(&An[r * STRIDE + lc]),
                               X + (size_t)(m0 + r) * BDIM + kof + lc);
                    cp_async16(smem_u32(&Bn[r * STRIDE + lc]),
                               Bbase + (size_t)r * BDIM + kof + lc);
                }
                asm volatile("cp.async.commit_group;\n");
            }

            #pragma unroll
            for (int kk = 0; kk < 4; ++kk) {
                const int kc = kk * 8 + l4;
                uint32_t bf[8][2];
                #pragma unroll
                for (int j = 0; j < 8; ++j) {
                    int n = wn * 64 + j * 8 + lg;
                    // raw fp32 bits: HW truncates to tf32 (no cvt ALU cost)
                    bf[j][0] = __float_as_uint(B[n * STRIDE + kc]);
                    bf[j][1] = __float_as_uint(B[n * STRIDE + kc + 4]);
                }
                #pragma unroll
                for (int mi = 0; mi < 2; ++mi) {
                    int r = wm * 32 + mi * 16 + lg;
                    uint32_t a0 = cvt_tf32(A[r * STRIDE + kc]);
                    uint32_t a1 = cvt_tf32(A[(r + 8) * STRIDE + kc]);
                    uint32_t a2 = cvt_tf32(A[r * STRIDE + kc + 4]);
                    uint32_t a3 = cvt_tf32(A[(r + 8) * STRIDE + kc + 4]);
                    #pragma unroll
                    for (int j = 0; j < 8; ++j) {
                        asm volatile(
                            "mma.sync.aligned.m16n8k8.row.col.f32.tf32.tf32.f32 "
                            "{%0,%1,%2,%3}, {%4,%5,%6,%7}, {%8,%9}, {%0,%1,%2,%3};\n"
                            : "+f"(acc[mi][j][0]), "+f"(acc[mi][j][1]),
                              "+f"(acc[mi][j][2]), "+f"(acc[mi][j][3])
                            : "r"(a0), "r"(a1), "r"(a2), "r"(a3),
                              "r"(bf[j][0]), "r"(bf[j][1]));
                    }
                }
            }
            __syncthreads();
        }

        // fused epilogue for this n-tile: tanh then dot with v, per-row partials
        #pragma unroll
        for (int mi = 0; mi < 2; ++mi) {
            #pragma unroll
            for (int j = 0; j < 8; ++j) {
                int c = nt * BN + wn * 64 + j * 8 + l4 * 2;
                float v0 = __ldg(&v[c]);
                float v1 = __ldg(&v[c + 1]);
                part[mi * 2 + 0] += v0 * fast_tanh(acc[mi][j][0])
                                  + v1 * fast_tanh(acc[mi][j][1]);
                part[mi * 2 + 1] += v0 * fast_tanh(acc[mi][j][2])
                                  + v1 * fast_tanh(acc[mi][j][3]);
            }
        }
    }

    // reduce the 4 lanes that share each row (same lg, l4 = 0..3)
    #pragma unroll
    for (int p = 0; p < 4; ++p) {
        part[p] += __shfl_xor_sync(0xffffffffu, part[p], 1);
        part[p] += __shfl_xor_sync(0xffffffffu, part[p], 2);
    }
    if (l4 == 0) {
        int rbase = wm * 32 + lg;
        atomicAdd(&rowsum[rbase + 0],  part[0]);
        atomicAdd(&rowsum[rbase + 8],  part[1]);
        atomicAdd(&rowsum[rbase + 16], part[2]);
        atomicAdd(&rowsum[rbase + 24], part[3]);
    }
    __syncthreads();
    if (tid < 128) g_logits[m0 + tid] = rowsum[tid];
}

// ---------------------------------------------------------------------------
// Kernel B: softmax over S=2048 per batch (bias b cancels: shift invariance).
// Also zero-fills the weighted-context region of d_out.
// ---------------------------------------------------------------------------
__global__ void softmax_kernel(float* __restrict__ out) {
    __shared__ float red[8];
    const int b = blockIdx.x;
    const int tid = threadIdx.x;
    const int warp = tid >> 5, lane = tid & 31;
    const float* lp = g_logits + b * SEQ;

    float vals[8];
    float m = -1e30f;
    #pragma unroll
    for (int i = 0; i < 8; ++i) {
        vals[i] = lp[i * 256 + tid];
        m = fmaxf(m, vals[i]);
    }
    #pragma unroll
    for (int o = 16; o > 0; o >>= 1) m = fmaxf(m, __shfl_xor_sync(~0u, m, o));
    if (lane == 0) red[warp] = m;
    __syncthreads();
    float bm = red[0];
    #pragma unroll
    for (int w = 1; w < 8; ++w) bm = fmaxf(bm, red[w]);
    __syncthreads();

    float s = 0.0f;
    #pragma unroll
    for (int i = 0; i < 8; ++i) {
        vals[i] = __expf(vals[i] - bm);
        s += vals[i];
    }
    #pragma unroll
    for (int o = 16; o > 0; o >>= 1) s += __shfl_xor_sync(~0u, s, o);
    if (lane == 0) red[warp] = s;
    __syncthreads();
    float ts = 0.0f;
    #pragma unroll
    for (int w = 0; w < 8; ++w) ts += red[w];

    float inv = 1.0f / ts;
    #pragma unroll
    for (int i = 0; i < 8; ++i)
        out[BATCH * BDIM + b * SEQ + i * 256 + tid] = vals[i] * inv;

    // zero weighted-context region (accumulated atomically by kernel C)
    for (int d = tid; d < BDIM; d += 256) out[b * BDIM + d] = 0.0f;
}

// ---------------------------------------------------------------------------
// Kernel C: weighted_context[b,d] = sum_s attn[b,s] * X[b,s,d]
// ---------------------------------------------------------------------------
__global__ void weighted_kernel(const float* __restrict__ X, float* __restrict__ out) {
    const int d  = blockIdx.x * 256 + threadIdx.x;
    const int b  = blockIdx.z;
    const int s0 = blockIdx.y * 512;
    const float* attn = out + BATCH * BDIM + b * SEQ;
    const float* xb = X + ((size_t)b * SEQ + s0) * BDIM + d;

    float a0 = 0.f, a1 = 0.f, a2 = 0.f, a3 = 0.f;
    for (int s = 0; s < 512; s += 4) {
        a0 += attn[s0 + s + 0] * xb[(size_t)(s + 0) * BDIM];
        a1 += attn[s0 + s + 1] * xb[(size_t)(s + 1) * BDIM];
        a2 += attn[s0 + s + 2] * xb[(size_t)(s + 2) * BDIM];
        a3 += attn[s0 + s + 3] * xb[(size_t)(s + 3) * BDIM];
    }
    atomicAdd(&out[b * BDIM + d], (a0 + a1) + (a2 + a3));
}

// ---------------------------------------------------------------------------
extern "C" void kernel_launch(void* const* d_in, const int* in_sizes, int n_in,
                              void* d_out, int out_size) {
    const float* X = (const float*)d_in[0];   // context [32,2048,1024]
    const float* W = (const float*)d_in[1];   // [1024,1024]
    const float* v = (const float*)d_in[2];   // [1024]
    // d_in[3] = b: irrelevant (softmax shift invariance)
    float* out = (float*)d_out;               // [wc 32*1024 | attn 32*2048]

    cudaFuncSetAttribute(logits_kernel,
                         cudaFuncAttributeMaxDynamicSharedMemorySize, SMEM_BYTES);

    logits_kernel<<<MROWS / BM, 256, SMEM_BYTES>>>(X, W, v);
    softmax_kernel<<<BATCH, 256>>>(out);
    weighted_kernel<<<dim3(4, 4, BATCH), 256>>>(X, out);
}

// round 5
// speedup vs baseline: 1.7361x; 1.5871x over previous
#include <cuda_runtime.h>
#include <cuda_fp16.h>
#include <cstdint>

#define BDIM   1024
#define BATCH  32
#define SEQ    2048
#define MROWS  (BATCH * SEQ)

#define BM 128
#define BN 128
#define BK 64                      // fp16: 64 halves = 128B row (swizzle atom)
#define KTILES (BDIM / BK)         // 16
#define NTILES (BDIM / BN)         // 8
#define GTOT   (NTILES * KTILES)   // 128 flat iterations
#define NSTG   3
#define STG_A     16384            // 128 rows x 128B
#define STG_BYTES 32768            // A + B
#define OFF_ROWSUM (NSTG * STG_BYTES)
#define SMEM_BYTES (OFF_ROWSUM + 512 + 128)

__device__ __half g_Xh[(size_t)MROWS * BDIM];   // 128 MiB fp16 mirror of X
__device__ __half g_Wh[BDIM * BDIM];
__device__ float  g_logits[MROWS];

__device__ __forceinline__ uint32_t smem_u32(const void* p) {
    return (uint32_t)__cvta_generic_to_shared(p);
}
__device__ __forceinline__ void cp_async16(uint32_t saddr, const void* gaddr) {
    asm volatile("cp.async.cg.shared.global [%0], [%1], 16;\n" :: "r"(saddr), "l"(gaddr));
}
__device__ __forceinline__ uint32_t swz(uint32_t off) {   // SW128: bits[6:4] ^= bits[9:7]
    return off ^ ((off >> 3) & 0x70u);
}
__device__ __forceinline__ float fast_tanh(float x) {
    float e = __expf(2.0f * x);
    return 1.0f - __fdividef(2.0f, e + 1.0f);
}
__device__ __forceinline__ void ldsm_x4(uint32_t& r0, uint32_t& r1, uint32_t& r2,
                                        uint32_t& r3, uint32_t addr) {
    asm volatile("ldmatrix.sync.aligned.m8n8.x4.shared.b16 {%0,%1,%2,%3}, [%4];"
                 : "=r"(r0), "=r"(r1), "=r"(r2), "=r"(r3) : "r"(addr));
}

// ---------------------------------------------------------------------------
// fp32 -> fp16 bulk convert (8 elems/thread, 16B stores)
// ---------------------------------------------------------------------------
__global__ void cvt_kernel(const float* __restrict__ src, __half* __restrict__ dst) {
    const size_t i = ((size_t)blockIdx.x * 256 + threadIdx.x) * 8;
    float4 f0 = *(const float4*)(src + i);
    float4 f1 = *(const float4*)(src + i + 4);
    __half2 h[4];
    h[0] = __float22half2_rn({f0.x, f0.y});
    h[1] = __float22half2_rn({f0.z, f0.w});
    h[2] = __float22half2_rn({f1.x, f1.y});
    h[3] = __float22half2_rn({f1.z, f1.w});
    *(uint4*)(dst + i) = *(uint4*)h;
}

// ---------------------------------------------------------------------------
// chunk loader: A tile (128 x 64 fp16) + B tile (128 x 64 fp16), SW128 smem.
// 8 cp.async per thread.
// ---------------------------------------------------------------------------
__device__ __forceinline__ void load_tile(char* smem, int g, int m0, int lr, int half_) {
    const int kt = g & (KTILES - 1);
    const int nt = g >> 4;
    const uint32_t base = smem_u32(smem) + (uint32_t)(g % NSTG) * STG_BYTES;
    const __half* Xb = g_Xh + (size_t)(m0 + lr) * BDIM + kt * BK + half_ * 32;
    const __half* Wb = g_Wh + (size_t)(nt * BN + lr) * BDIM + kt * BK + half_ * 32;
    #pragma unroll
    for (int i = 0; i < 4; ++i) {
        uint32_t off = (uint32_t)lr * 128u + (uint32_t)half_ * 64u + (uint32_t)i * 16u;
        uint32_t sw = swz(off);
        cp_async16(base + sw,         Xb + i * 8);
        cp_async16(base + STG_A + sw, Wb + i * 8);
    }
    asm volatile("cp.async.commit_group;\n" ::: "memory");
}

// ---------------------------------------------------------------------------
// Kernel A: logits[m] = sum_e v[e] * tanh( sum_d X[m,d] W[e,d] )
// fp16 m16n8k16 mma + ldmatrix fragments, 3-stage cp.async pipeline,
// fused tanh + v-dot epilogue per n-pass.
// ---------------------------------------------------------------------------
__global__ __launch_bounds__(256, 2)
void logits_kernel(const float* __restrict__ v) {
    extern __shared__ char smem[];
    float* rowsum = (float*)(smem + OFF_ROWSUM);

    const int tid  = threadIdx.x;
    const int warp = tid >> 5;
    const int lane = tid & 31;
    const int wm = warp >> 1;           // 0..3  -> 32-row group
    const int wn = warp & 1;            // 0..1  -> 64-col group
    const int l4 = lane & 3;
    const int lg = lane >> 2;
    const int m0 = blockIdx.x * BM;

    if (tid < 128) rowsum[tid] = 0.0f;

    const int lr = tid >> 1;            // loader row 0..127
    const int half_ = tid & 1;          // loader 64B half

    const uint32_t sb = smem_u32(smem);
    // ldmatrix base addresses (per-lane, within a stage)
    // A: row = wm*32 + mi*16 + (lane&15), byte col = ks*32 + (lane>>4)*16
    const uint32_t a_row = (uint32_t)(wm * 32 + (lane & 15));
    const uint32_t a_kb  = (uint32_t)((lane >> 4) * 16);
    // B: row = wn*64 + j*16 + (sel>>1)*8 + idx, byte col = ks*32 + (sel&1)*16
    const uint32_t b_idx = (uint32_t)(lane & 7);
    const uint32_t b_sel = (uint32_t)(lane >> 3);
    const uint32_t b_row = (uint32_t)(wn * 64 + (b_sel >> 1) * 8) + b_idx;
    const uint32_t b_kb  = (b_sel & 1) * 16u;

    // prologue: stages 0..2
    load_tile(smem, 0, m0, lr, half_);
    load_tile(smem, 1, m0, lr, half_);
    load_tile(smem, 2, m0, lr, half_);

    float part[4] = {0.f, 0.f, 0.f, 0.f};
    float acc[2][8][4];

    for (int g = 0; g < GTOT; ++g) {
        const int kt = g & (KTILES - 1);
        const int nt = g >> 4;

        if (kt == 0) {
            #pragma unroll
            for (int i = 0; i < 2; ++i)
                #pragma unroll
                for (int j = 0; j < 8; ++j)
                    #pragma unroll
                    for (int q = 0; q < 4; ++q) acc[i][j][q] = 0.0f;
        }

        if (g < GTOT - 2)       asm volatile("cp.async.wait_group 2;" ::: "memory");
        else if (g == GTOT - 2) asm volatile("cp.async.wait_group 1;" ::: "memory");
        else                    asm volatile("cp.async.wait_group 0;" ::: "memory");
        __syncthreads();

        const uint32_t stage = sb + (uint32_t)(g % NSTG) * STG_BYTES;

        #pragma unroll
        for (int ks = 0; ks < 4; ++ks) {
            // A fragments: 2 m-tiles
            uint32_t a[2][4];
            #pragma unroll
            for (int mi = 0; mi < 2; ++mi) {
                uint32_t off = (a_row + mi * 16u) * 128u + (uint32_t)(ks * 32) + a_kb;
                ldsm_x4(a[mi][0], a[mi][1], a[mi][2], a[mi][3], stage + swz(off));
            }
            // B fragments: 8 n-tiles (4 x ldmatrix.x4)
            uint32_t b[8][2];
            #pragma unroll
            for (int j = 0; j < 4; ++j) {
                uint32_t off = (b_row + j * 16u) * 128u + (uint32_t)(ks * 32) + b_kb;
                ldsm_x4(b[2*j][0], b[2*j][1], b[2*j+1][0], b[2*j+1][1],
                        stage + STG_A + swz(off));
            }
            #pragma unroll
            for (int mi = 0; mi < 2; ++mi) {
                #pragma unroll
                for (int j = 0; j < 8; ++j) {
                    asm volatile(
                        "mma.sync.aligned.m16n8k16.row.col.f32.f16.f16.f32 "
                        "{%0,%1,%2,%3}, {%4,%5,%6,%7}, {%8,%9}, {%0,%1,%2,%3};\n"
                        : "+f"(acc[mi][j][0]), "+f"(acc[mi][j][1]),
                          "+f"(acc[mi][j][2]), "+f"(acc[mi][j][3])
                        : "r"(a[mi][0]), "r"(a[mi][1]), "r"(a[mi][2]), "r"(a[mi][3]),
                          "r"(b[j][0]), "r"(b[j][1]));
                }
            }
        }
        __syncthreads();

        if (g + 3 < GTOT) load_tile(smem, g + 3, m0, lr, half_);

        // pass epilogue: tanh + v-dot
        if (kt == KTILES - 1) {
            #pragma unroll
            for (int mi = 0; mi < 2; ++mi) {
                #pragma unroll
                for (int j = 0; j < 8; ++j) {
                    int c = nt * BN + wn * 64 + j * 8 + l4 * 2;
                    float v0 = __ldg(&v[c]);
                    float v1 = __ldg(&v[c + 1]);
                    part[mi * 2 + 0] += v0 * fast_tanh(acc[mi][j][0])
                                      + v1 * fast_tanh(acc[mi][j][1]);
                    part[mi * 2 + 1] += v0 * fast_tanh(acc[mi][j][2])
                                      + v1 * fast_tanh(acc[mi][j][3]);
                }
            }
        }
    }

    // reduce across the 4 lanes sharing each row, then across the 2 wn warps
    #pragma unroll
    for (int p = 0; p < 4; ++p) {
        part[p] += __shfl_xor_sync(0xffffffffu, part[p], 1);
        part[p] += __shfl_xor_sync(0xffffffffu, part[p], 2);
    }
    if (l4 == 0) {
        int rbase = wm * 32 + lg;
        atomicAdd(&rowsum[rbase + 0],  part[0]);
        atomicAdd(&rowsum[rbase + 8],  part[1]);
        atomicAdd(&rowsum[rbase + 16], part[2]);
        atomicAdd(&rowsum[rbase + 24], part[3]);
    }
    __syncthreads();
    if (tid < 128) g_logits[m0 + tid] = rowsum[tid];
}

// ---------------------------------------------------------------------------
// Kernel B: softmax over S=2048 per batch (bias b cancels). Zeroes wc region.
// ---------------------------------------------------------------------------
__global__ void softmax_kernel(float* __restrict__ out) {
    __shared__ float red[8];
    const int b = blockIdx.x;
    const int tid = threadIdx.x;
    const int warp = tid >> 5, lane = tid & 31;
    const float* lp = g_logits + b * SEQ;

    float vals[8];
    float m = -1e30f;
    #pragma unroll
    for (int i = 0; i < 8; ++i) { vals[i] = lp[i * 256 + tid]; m = fmaxf(m, vals[i]); }
    #pragma unroll
    for (int o = 16; o > 0; o >>= 1) m = fmaxf(m, __shfl_xor_sync(~0u, m, o));
    if (lane == 0) red[warp] = m;
    __syncthreads();
    float bm = red[0];
    #pragma unroll
    for (int w = 1; w < 8; ++w) bm = fmaxf(bm, red[w]);
    __syncthreads();

    float s = 0.0f;
    #pragma unroll
    for (int i = 0; i < 8; ++i) { vals[i] = __expf(vals[i] - bm); s += vals[i]; }
    #pragma unroll
    for (int o = 16; o > 0; o >>= 1) s += __shfl_xor_sync(~0u, s, o);
    if (lane == 0) red[warp] = s;
    __syncthreads();
    float ts = 0.0f;
    #pragma unroll
    for (int w = 0; w < 8; ++w) ts += red[w];

    float inv = 1.0f / ts;
    #pragma unroll
    for (int i = 0; i < 8; ++i)
        out[BATCH * BDIM + b * SEQ + i * 256 + tid] = vals[i] * inv;

    for (int d = tid; d < BDIM; d += 256) out[b * BDIM + d] = 0.0f;
}

// ---------------------------------------------------------------------------
// Kernel C: weighted_context[b,d] = sum_s attn[b,s] * X[b,s,d]
// ---------------------------------------------------------------------------
__global__ void weighted_kernel(const float* __restrict__ X, float* __restrict__ out) {
    const int d  = blockIdx.x * 256 + threadIdx.x;
    const int b  = blockIdx.z;
    const int s0 = blockIdx.y * 512;
    const float* attn = out + BATCH * BDIM + b * SEQ;
    const float* xb = X + ((size_t)b * SEQ + s0) * BDIM + d;

    float a0 = 0.f, a1 = 0.f, a2 = 0.f, a3 = 0.f;
    for (int s = 0; s < 512; s += 4) {
        a0 += attn[s0 + s + 0] * xb[(size_t)(s + 0) * BDIM];
        a1 += attn[s0 + s + 1] * xb[(size_t)(s + 1) * BDIM];
        a2 += attn[s0 + s + 2] * xb[(size_t)(s + 2) * BDIM];
        a3 += attn[s0 + s + 3] * xb[(size_t)(s + 3) * BDIM];
    }
    atomicAdd(&out[b * BDIM + d], (a0 + a1) + (a2 + a3));
}

// ---------------------------------------------------------------------------
extern "C" void kernel_launch(void* const* d_in, const int* in_sizes, int n_in,
                              void* d_out, int out_size) {
    const float* X = (const float*)d_in[0];   // context [32,2048,1024]
    const float* W = (const float*)d_in[1];   // [1024,1024]
    const float* v = (const float*)d_in[2];   // [1024]
    float* out = (float*)d_out;               // [wc 32*1024 | attn 32*2048]

    __half* Xh; cudaGetSymbolAddress((void**)&Xh, g_Xh);
    __half* Wh; cudaGetSymbolAddress((void**)&Wh, g_Wh);

    cvt_kernel<<<(MROWS * (BDIM / 8)) / 256, 256>>>(X, Xh);   // 32768 blocks
    cvt_kernel<<<(BDIM * (BDIM / 8)) / 256, 256>>>(W, Wh);    // 512 blocks

    cudaFuncSetAttribute(logits_kernel,
                         cudaFuncAttributeMaxDynamicSharedMemorySize, SMEM_BYTES);
    logits_kernel<<<MROWS / BM, 256, SMEM_BYTES>>>(v);
    softmax_kernel<<<BATCH, 256>>>(out);
    weighted_kernel<<<dim3(4, 4, BATCH), 256>>>(X, out);
}

// round 6
// speedup vs baseline: 1.8015x; 1.0376x over previous
#include <cuda_runtime.h>
#include <cuda_fp16.h>
#include <cstdint>

#define BDIM   1024
#define BATCH  32
#define SEQ    2048
#define MROWS  (BATCH * SEQ)

#define BM 128
#define BN 128
#define BK 64                      // fp16: 64 halves = 128B row (swizzle atom)
#define KTILES (BDIM / BK)         // 16
#define NTILES (BDIM / BN)         // 8
#define GTOT   (NTILES * KTILES)   // 128 flat iterations
#define NSTG   3
#define STG_A     16384            // 128 rows x 128B
#define STG_BYTES 32768            // A + B
#define OFF_ROWSUM (NSTG * STG_BYTES)
#define SMEM_BYTES (OFF_ROWSUM + 512 + 128)

#define XBLOCKS ((MROWS * (BDIM / 8)) / 256)   // 32768
#define WBLOCKS ((BDIM * (BDIM / 8)) / 256)    // 512

__device__ __half g_Xh[(size_t)MROWS * BDIM];   // 128 MiB fp16 mirror of X
__device__ __half g_Wh[BDIM * BDIM];
__device__ float  g_logits[MROWS];

__device__ __forceinline__ uint32_t smem_u32(const void* p) {
    return (uint32_t)__cvta_generic_to_shared(p);
}
__device__ __forceinline__ void cp_async16(uint32_t saddr, const void* gaddr) {
    asm volatile("cp.async.cg.shared.global [%0], [%1], 16;\n" :: "r"(saddr), "l"(gaddr));
}
__device__ __forceinline__ uint32_t swz(uint32_t off) {   // SW128: bits[6:4] ^= bits[9:7]
    return off ^ ((off >> 3) & 0x70u);
}
__device__ __forceinline__ float fast_tanh(float x) {
    float e = __expf(2.0f * x);
    return 1.0f - __fdividef(2.0f, e + 1.0f);
}
__device__ __forceinline__ void ldsm_x4(uint32_t& r0, uint32_t& r1, uint32_t& r2,
                                        uint32_t& r3, uint32_t addr) {
    asm volatile("ldmatrix.sync.aligned.m8n8.x4.shared.b16 {%0,%1,%2,%3}, [%4];"
                 : "=r"(r0), "=r"(r1), "=r"(r2), "=r"(r3) : "r"(addr));
}

// ---------------------------------------------------------------------------
// fp32 -> fp16 bulk convert of X and W in ONE launch (8 elems/thread)
// ---------------------------------------------------------------------------
__global__ void cvt_all_kernel(const float* __restrict__ X, const float* __restrict__ W) {
    const float* src;
    __half* dst;
    size_t i;
    if (blockIdx.x < XBLOCKS) {
        src = X; dst = g_Xh;
        i = ((size_t)blockIdx.x * 256 + threadIdx.x) * 8;
    } else {
        src = W; dst = g_Wh;
        i = ((size_t)(blockIdx.x - XBLOCKS) * 256 + threadIdx.x) * 8;
    }
    float4 f0 = *(const float4*)(src + i);
    float4 f1 = *(const float4*)(src + i + 4);
    __half2 h[4];
    h[0] = __float22half2_rn({f0.x, f0.y});
    h[1] = __float22half2_rn({f0.z, f0.w});
    h[2] = __float22half2_rn({f1.x, f1.y});
    h[3] = __float22half2_rn({f1.z, f1.w});
    *(uint4*)(dst + i) = *(uint4*)h;
}

// ---------------------------------------------------------------------------
// tile loader: A (128 x 64 fp16) + B (128 x 64 fp16), SW128 smem.
// ---------------------------------------------------------------------------
__device__ __forceinline__ void load_tile(char* smem, int g, int m0, int lr, int half_) {
    const int kt = g & (KTILES - 1);
    const int nt = g >> 4;
    const uint32_t base = smem_u32(smem) + (uint32_t)(g % NSTG) * STG_BYTES;
    const __half* Xb = g_Xh + (size_t)(m0 + lr) * BDIM + kt * BK + half_ * 32;
    const __half* Wb = g_Wh + (size_t)(nt * BN + lr) * BDIM + kt * BK + half_ * 32;
    #pragma unroll
    for (int i = 0; i < 4; ++i) {
        uint32_t off = (uint32_t)lr * 128u + (uint32_t)half_ * 64u + (uint32_t)i * 16u;
        uint32_t sw = swz(off);
        cp_async16(base + sw,         Xb + i * 8);
        cp_async16(base + STG_A + sw, Wb + i * 8);
    }
    asm volatile("cp.async.commit_group;\n" ::: "memory");
}

// ---------------------------------------------------------------------------
// Kernel A: logits[m] = sum_e v[e] * tanh( sum_d X[m,d] W[e,d] )
// fp16 m16n8k16 + ldmatrix, 3-stage ring, ONE __syncthreads per iteration,
// loads issued 2 tiles ahead BEFORE the MMAs. Fused tanh + v-dot epilogue.
// ---------------------------------------------------------------------------
__global__ __launch_bounds__(256, 2)
void logits_kernel(const float* __restrict__ v) {
    extern __shared__ char smem[];
    float* rowsum = (float*)(smem + OFF_ROWSUM);

    const int tid  = threadIdx.x;
    const int warp = tid >> 5;
    const int lane = tid & 31;
    const int wm = warp >> 1;           // 0..3  -> 32-row group
    const int wn = warp & 1;            // 0..1  -> 64-col group
    const int l4 = lane & 3;
    const int lg = lane >> 2;
    const int m0 = blockIdx.x * BM;

    if (tid < 128) rowsum[tid] = 0.0f;

    const int lr = tid >> 1;            // loader row 0..127
    const int half_ = tid & 1;          // loader 64B half

    const uint32_t sb = smem_u32(smem);
    const uint32_t a_row = (uint32_t)(wm * 32 + (lane & 15));
    const uint32_t a_kb  = (uint32_t)((lane >> 4) * 16);
    const uint32_t b_idx = (uint32_t)(lane & 7);
    const uint32_t b_sel = (uint32_t)(lane >> 3);
    const uint32_t b_row = (uint32_t)(wn * 64 + (b_sel >> 1) * 8) + b_idx;
    const uint32_t b_kb  = (b_sel & 1) * 16u;

    // prologue: tiles 0, 1
    load_tile(smem, 0, m0, lr, half_);
    load_tile(smem, 1, m0, lr, half_);

    float part[4] = {0.f, 0.f, 0.f, 0.f};
    float acc[2][8][4];

    for (int g = 0; g < GTOT; ++g) {
        const int kt = g & (KTILES - 1);
        const int nt = g >> 4;

        if (kt == 0) {
            #pragma unroll
            for (int i = 0; i < 2; ++i)
                #pragma unroll
                for (int j = 0; j < 8; ++j)
                    #pragma unroll
                    for (int q = 0; q < 4; ++q) acc[i][j][q] = 0.0f;
        }

        // tile g ready (newest committed tile is g+1 -> allow 1 pending)
        if (g < GTOT - 1) asm volatile("cp.async.wait_group 1;" ::: "memory");
        else              asm volatile("cp.async.wait_group 0;" ::: "memory");
        // all warps are past iteration g-1 -> buffer (g+2)%3 is reusable
        __syncthreads();

        if (g + 2 < GTOT) load_tile(smem, g + 2, m0, lr, half_);

        const uint32_t stage = sb + (uint32_t)(g % NSTG) * STG_BYTES;

        #pragma unroll
        for (int ks = 0; ks < 4; ++ks) {
            uint32_t a[2][4];
            #pragma unroll
            for (int mi = 0; mi < 2; ++mi) {
                uint32_t off = (a_row + mi * 16u) * 128u + (uint32_t)(ks * 32) + a_kb;
                ldsm_x4(a[mi][0], a[mi][1], a[mi][2], a[mi][3], stage + swz(off));
            }
            uint32_t b[8][2];
            #pragma unroll
            for (int j = 0; j < 4; ++j) {
                uint32_t off = (b_row + j * 16u) * 128u + (uint32_t)(ks * 32) + b_kb;
                ldsm_x4(b[2*j][0], b[2*j][1], b[2*j+1][0], b[2*j+1][1],
                        stage + STG_A + swz(off));
            }
            #pragma unroll
            for (int mi = 0; mi < 2; ++mi) {
                #pragma unroll
                for (int j = 0; j < 8; ++j) {
                    asm volatile(
                        "mma.sync.aligned.m16n8k16.row.col.f32.f16.f16.f32 "
                        "{%0,%1,%2,%3}, {%4,%5,%6,%7}, {%8,%9}, {%0,%1,%2,%3};\n"
                        : "+f"(acc[mi][j][0]), "+f"(acc[mi][j][1]),
                          "+f"(acc[mi][j][2]), "+f"(acc[mi][j][3])
                        : "r"(a[mi][0]), "r"(a[mi][1]), "r"(a[mi][2]), "r"(a[mi][3]),
                          "r"(b[j][0]), "r"(b[j][1]));
                }
            }
        }

        // pass epilogue (register-only; no smem hazard)
        if (kt == KTILES - 1) {
            #pragma unroll
            for (int mi = 0; mi < 2; ++mi) {
                #pragma unroll
                for (int j = 0; j < 8; ++j) {
                    int c = nt * BN + wn * 64 + j * 8 + l4 * 2;
                    float v0 = __ldg(&v[c]);
                    float v1 = __ldg(&v[c + 1]);
                    part[mi * 2 + 0] += v0 * fast_tanh(acc[mi][j][0])
                                      + v1 * fast_tanh(acc[mi][j][1]);
                    part[mi * 2 + 1] += v0 * fast_tanh(acc[mi][j][2])
                                      + v1 * fast_tanh(acc[mi][j][3]);
                }
            }
        }
    }

    #pragma unroll
    for (int p = 0; p < 4; ++p) {
        part[p] += __shfl_xor_sync(0xffffffffu, part[p], 1);
        part[p] += __shfl_xor_sync(0xffffffffu, part[p], 2);
    }
    if (l4 == 0) {
        int rbase = wm * 32 + lg;
        atomicAdd(&rowsum[rbase + 0],  part[0]);
        atomicAdd(&rowsum[rbase + 8],  part[1]);
        atomicAdd(&rowsum[rbase + 16], part[2]);
        atomicAdd(&rowsum[rbase + 24], part[3]);
    }
    __syncthreads();
    if (tid < 128) g_logits[m0 + tid] = rowsum[tid];
}

// ---------------------------------------------------------------------------
// Kernel B: softmax over S=2048 per batch (bias b cancels). Zeroes wc region.
// ---------------------------------------------------------------------------
__global__ void softmax_kernel(float* __restrict__ out) {
    __shared__ float red[8];
    const int b = blockIdx.x;
    const int tid = threadIdx.x;
    const int warp = tid >> 5, lane = tid & 31;
    const float* lp = g_logits + b * SEQ;

    float vals[8];
    float m = -1e30f;
    #pragma unroll
    for (int i = 0; i < 8; ++i) { vals[i] = lp[i * 256 + tid]; m = fmaxf(m, vals[i]); }
    #pragma unroll
    for (int o = 16; o > 0; o >>= 1) m = fmaxf(m, __shfl_xor_sync(~0u, m, o));
    if (lane == 0) red[warp] = m;
    __syncthreads();
    float bm = red[0];
    #pragma unroll
    for (int w = 1; w < 8; ++w) bm = fmaxf(bm, red[w]);
    __syncthreads();

    float s = 0.0f;
    #pragma unroll
    for (int i = 0; i < 8; ++i) { vals[i] = __expf(vals[i] - bm); s += vals[i]; }
    #pragma unroll
    for (int o = 16; o > 0; o >>= 1) s += __shfl_xor_sync(~0u, s, o);
    if (lane == 0) red[warp] = s;
    __syncthreads();
    float ts = 0.0f;
    #pragma unroll
    for (int w = 0; w < 8; ++w) ts += red[w];

    float inv = 1.0f / ts;
    #pragma unroll
    for (int i = 0; i < 8; ++i)
        out[BATCH * BDIM + b * SEQ + i * 256 + tid] = vals[i] * inv;

    for (int d = tid; d < BDIM; d += 256) out[b * BDIM + d] = 0.0f;
}

// ---------------------------------------------------------------------------
// Kernel C: weighted_context[b,d] = sum_s attn[b,s] * X[b,s,d]
// reads the fp16 mirror (half the DRAM traffic), 2 d's per thread.
// ---------------------------------------------------------------------------
__global__ void weighted_kernel(float* __restrict__ out) {
    const int d2 = (blockIdx.x * 256 + threadIdx.x) * 2;   // 2 halves
    const int b  = blockIdx.z;
    const int s0 = blockIdx.y * 512;
    const float* attn = out + BATCH * BDIM + b * SEQ + s0;
    const __half2* xb = (const __half2*)(g_Xh + ((size_t)b * SEQ + s0) * BDIM + d2);

    float a0 = 0.f, a1 = 0.f;
    #pragma unroll 8
    for (int s = 0; s < 512; ++s) {
        float2 x = __half22float2(xb[(size_t)s * (BDIM / 2)]);
        float w = attn[s];
        a0 += w * x.x;
        a1 += w * x.y;
    }
    atomicAdd(&out[b * BDIM + d2],     a0);
    atomicAdd(&out[b * BDIM + d2 + 1], a1);
}

// ---------------------------------------------------------------------------
extern "C" void kernel_launch(void* const* d_in, const int* in_sizes, int n_in,
                              void* d_out, int out_size) {
    const float* X = (const float*)d_in[0];   // context [32,2048,1024]
    const float* W = (const float*)d_in[1];   // [1024,1024]
    const float* v = (const float*)d_in[2];   // [1024]
    float* out = (float*)d_out;               // [wc 32*1024 | attn 32*2048]

    cvt_all_kernel<<<XBLOCKS + WBLOCKS, 256>>>(X, W);

    cudaFuncSetAttribute(logits_kernel,
                         cudaFuncAttributeMaxDynamicSharedMemorySize, SMEM_BYTES);
    logits_kernel<<<MROWS / BM, 256, SMEM_BYTES>>>(v);
    softmax_kernel<<<BATCH, 256>>>(out);
    weighted_kernel<<<dim3(2, 4, BATCH), 256>>>(out);
}

// round 7
// speedup vs baseline: 1.8241x; 1.0126x over previous
#include <cuda_runtime.h>
#include <cuda_fp16.h>
#include <cstdint>

#define BDIM   1024
#define BATCH  32
#define SEQ    2048
#define MROWS  (BATCH * SEQ)

#define BM 128
#define BN 128
#define BK 64                      // fp16: 64 halves = 128B row (swizzle atom)
#define KTILES (BDIM / BK)         // 16
#define NTILES (BDIM / BN)         // 8
#define GTOT   (NTILES * KTILES)   // 128 flat iterations
#define NSTG   3
#define STG_A     16384            // 128 rows x 128B
#define STG_BYTES 32768            // A + B
#define OFF_ROWSUM (NSTG * STG_BYTES)
#define OFF_V      (OFF_ROWSUM + 512)
#define SMEM_BYTES (OFF_V + BDIM * 4 + 128)

#define XBLOCKS ((MROWS * (BDIM / 8)) / 256)   // 32768
#define WBLOCKS ((BDIM * (BDIM / 8)) / 256)    // 512

__device__ __half g_Xh[(size_t)MROWS * BDIM];   // 128 MiB fp16 mirror of X
__device__ __half g_Wh[BDIM * BDIM];
__device__ float  g_logits[MROWS];

__device__ __forceinline__ uint32_t smem_u32(const void* p) {
    return (uint32_t)__cvta_generic_to_shared(p);
}
__device__ __forceinline__ void cp_async16(uint32_t saddr, const void* gaddr) {
    asm volatile("cp.async.cg.shared.global [%0], [%1], 16;\n" :: "r"(saddr), "l"(gaddr));
}
__device__ __forceinline__ uint32_t swz(uint32_t off) {   // SW128: bits[6:4] ^= bits[9:7]
    return off ^ ((off >> 3) & 0x70u);
}
__device__ __forceinline__ float fast_tanh(float x) {
    float e = __expf(2.0f * x);
    return 1.0f - __fdividef(2.0f, e + 1.0f);
}
__device__ __forceinline__ void ldsm_x4(uint32_t& r0, uint32_t& r1, uint32_t& r2,
                                        uint32_t& r3, uint32_t addr) {
    asm volatile("ldmatrix.sync.aligned.m8n8.x4.shared.b16 {%0,%1,%2,%3}, [%4];"
                 : "=r"(r0), "=r"(r1), "=r"(r2), "=r"(r3) : "r"(addr));
}

// ---------------------------------------------------------------------------
// no-op kernel: shifts ncu capture alignment so -s 5 lands on logits_kernel
// ---------------------------------------------------------------------------
__global__ void noop_kernel() {}

// ---------------------------------------------------------------------------
// fp32 -> fp16 bulk convert of X and W in ONE launch (8 elems/thread)
// ---------------------------------------------------------------------------
__global__ void cvt_all_kernel(const float* __restrict__ X, const float* __restrict__ W) {
    const float* src;
    __half* dst;
    size_t i;
    if (blockIdx.x < XBLOCKS) {
        src = X; dst = g_Xh;
        i = ((size_t)blockIdx.x * 256 + threadIdx.x) * 8;
    } else {
        src = W; dst = g_Wh;
        i = ((size_t)(blockIdx.x - XBLOCKS) * 256 + threadIdx.x) * 8;
    }
    float4 f0 = *(const float4*)(src + i);
    float4 f1 = *(const float4*)(src + i + 4);
    __half2 h[4];
    h[0] = __float22half2_rn({f0.x, f0.y});
    h[1] = __float22half2_rn({f0.z, f0.w});
    h[2] = __float22half2_rn({f1.x, f1.y});
    h[3] = __float22half2_rn({f1.z, f1.w});
    *(uint4*)(dst + i) = *(uint4*)h;
}

// ---------------------------------------------------------------------------
// tile loader: A (128 x 64 fp16) + B (128 x 64 fp16), SW128 smem.
// ---------------------------------------------------------------------------
__device__ __forceinline__ void load_tile(char* smem, int g, int m0, int lr, int half_) {
    const int kt = g & (KTILES - 1);
    const int nt = g >> 4;
    const uint32_t base = smem_u32(smem) + (uint32_t)(g % NSTG) * STG_BYTES;
    const __half* Xb = g_Xh + (size_t)(m0 + lr) * BDIM + kt * BK + half_ * 32;
    const __half* Wb = g_Wh + (size_t)(nt * BN + lr) * BDIM + kt * BK + half_ * 32;
    #pragma unroll
    for (int i = 0; i < 4; ++i) {
        uint32_t off = (uint32_t)lr * 128u + (uint32_t)half_ * 64u + (uint32_t)i * 16u;
        uint32_t sw = swz(off);
        cp_async16(base + sw,         Xb + i * 8);
        cp_async16(base + STG_A + sw, Wb + i * 8);
    }
    asm volatile("cp.async.commit_group;\n" ::: "memory");
}

// ---------------------------------------------------------------------------
// Kernel A: logits[m] = sum_e v[e] * tanh( sum_d X[m,d] W[e,d] )
// fp16 m16n8k16 + ldmatrix, 3-stage ring, one __syncthreads per iteration,
// loads issued 2 tiles ahead BEFORE the MMAs. Fused tanh + v-dot epilogue.
// ---------------------------------------------------------------------------
__global__ __launch_bounds__(256, 2)
void logits_kernel(const float* __restrict__ v) {
    extern __shared__ char smem[];
    float* rowsum = (float*)(smem + OFF_ROWSUM);
    float* vs     = (float*)(smem + OFF_V);

    const int tid  = threadIdx.x;
    const int warp = tid >> 5;
    const int lane = tid & 31;
    const int wm = warp >> 1;           // 0..3  -> 32-row group
    const int wn = warp & 1;            // 0..1  -> 64-col group
    const int l4 = lane & 3;
    const int lg = lane >> 2;
    const int m0 = blockIdx.x * BM;

    if (tid < 128) rowsum[tid] = 0.0f;
    #pragma unroll
    for (int i = 0; i < 4; ++i) vs[tid + 256 * i] = v[tid + 256 * i];

    const int lr = tid >> 1;            // loader row 0..127
    const int half_ = tid & 1;          // loader 64B half

    const uint32_t sb = smem_u32(smem);
    const uint32_t a_row = (uint32_t)(wm * 32 + (lane & 15));
    const uint32_t a_kb  = (uint32_t)((lane >> 4) * 16);
    const uint32_t b_idx = (uint32_t)(lane & 7);
    const uint32_t b_sel = (uint32_t)(lane >> 3);
    const uint32_t b_row = (uint32_t)(wn * 64 + (b_sel >> 1) * 8) + b_idx;
    const uint32_t b_kb  = (b_sel & 1) * 16u;

    // prologue: tiles 0, 1
    load_tile(smem, 0, m0, lr, half_);
    load_tile(smem, 1, m0, lr, half_);

    float part[4] = {0.f, 0.f, 0.f, 0.f};
    float acc[2][8][4];

    for (int g = 0; g < GTOT; ++g) {
        const int kt = g & (KTILES - 1);
        const int nt = g >> 4;

        if (kt == 0) {
            #pragma unroll
            for (int i = 0; i < 2; ++i)
                #pragma unroll
                for (int j = 0; j < 8; ++j)
                    #pragma unroll
                    for (int q = 0; q < 4; ++q) acc[i][j][q] = 0.0f;
        }

        if (g < GTOT - 1) asm volatile("cp.async.wait_group 1;" ::: "memory");
        else              asm volatile("cp.async.wait_group 0;" ::: "memory");
        __syncthreads();

        if (g + 2 < GTOT) load_tile(smem, g + 2, m0, lr, half_);

        const uint32_t stage = sb + (uint32_t)(g % NSTG) * STG_BYTES;

        #pragma unroll
        for (int ks = 0; ks < 4; ++ks) {
            uint32_t a[2][4];
            #pragma unroll
            for (int mi = 0; mi < 2; ++mi) {
                uint32_t off = (a_row + mi * 16u) * 128u + (uint32_t)(ks * 32) + a_kb;
                ldsm_x4(a[mi][0], a[mi][1], a[mi][2], a[mi][3], stage + swz(off));
            }
            uint32_t b[8][2];
            #pragma unroll
            for (int j = 0; j < 4; ++j) {
                uint32_t off = (b_row + j * 16u) * 128u + (uint32_t)(ks * 32) + b_kb;
                ldsm_x4(b[2*j][0], b[2*j][1], b[2*j+1][0], b[2*j+1][1],
                        stage + STG_A + swz(off));
            }
            #pragma unroll
            for (int mi = 0; mi < 2; ++mi) {
                #pragma unroll
                for (int j = 0; j < 8; ++j) {
                    asm volatile(
                        "mma.sync.aligned.m16n8k16.row.col.f32.f16.f16.f32 "
                        "{%0,%1,%2,%3}, {%4,%5,%6,%7}, {%8,%9}, {%0,%1,%2,%3};\n"
                        : "+f"(acc[mi][j][0]), "+f"(acc[mi][j][1]),
                          "+f"(acc[mi][j][2]), "+f"(acc[mi][j][3])
                        : "r"(a[mi][0]), "r"(a[mi][1]), "r"(a[mi][2]), "r"(a[mi][3]),
                          "r"(b[j][0]), "r"(b[j][1]));
                }
            }
        }

        if (kt == KTILES - 1) {
            #pragma unroll
            for (int mi = 0; mi < 2; ++mi) {
                #pragma unroll
                for (int j = 0; j < 8; ++j) {
                    int c = nt * BN + wn * 64 + j * 8 + l4 * 2;
                    float v0 = vs[c];
                    float v1 = vs[c + 1];
                    part[mi * 2 + 0] += v0 * fast_tanh(acc[mi][j][0])
                                      + v1 * fast_tanh(acc[mi][j][1]);
                    part[mi * 2 + 1] += v0 * fast_tanh(acc[mi][j][2])
                                      + v1 * fast_tanh(acc[mi][j][3]);
                }
            }
        }
    }

    #pragma unroll
    for (int p = 0; p < 4; ++p) {
        part[p] += __shfl_xor_sync(0xffffffffu, part[p], 1);
        part[p] += __shfl_xor_sync(0xffffffffu, part[p], 2);
    }
    if (l4 == 0) {
        int rbase = wm * 32 + lg;
        atomicAdd(&rowsum[rbase + 0],  part[0]);
        atomicAdd(&rowsum[rbase + 8],  part[1]);
        atomicAdd(&rowsum[rbase + 16], part[2]);
        atomicAdd(&rowsum[rbase + 24], part[3]);
    }
    __syncthreads();
    if (tid < 128) g_logits[m0 + tid] = rowsum[tid];
}

// ---------------------------------------------------------------------------
// Kernel B: softmax over S=2048 per batch (bias b cancels). Zeroes wc region.
// ---------------------------------------------------------------------------
__global__ void softmax_kernel(float* __restrict__ out) {
    __shared__ float red[8];
    const int b = blockIdx.x;
    const int tid = threadIdx.x;
    const int warp = tid >> 5, lane = tid & 31;
    const float* lp = g_logits + b * SEQ;

    float vals[8];
    float m = -1e30f;
    #pragma unroll
    for (int i = 0; i < 8; ++i) { vals[i] = lp[i * 256 + tid]; m = fmaxf(m, vals[i]); }
    #pragma unroll
    for (int o = 16; o > 0; o >>= 1) m = fmaxf(m, __shfl_xor_sync(~0u, m, o));
    if (lane == 0) red[warp] = m;
    __syncthreads();
    float bm = red[0];
    #pragma unroll
    for (int w = 1; w < 8; ++w) bm = fmaxf(bm, red[w]);
    __syncthreads();

    float s = 0.0f;
    #pragma unroll
    for (int i = 0; i < 8; ++i) { vals[i] = __expf(vals[i] - bm); s += vals[i]; }
    #pragma unroll
    for (int o = 16; o > 0; o >>= 1) s += __shfl_xor_sync(~0u, s, o);
    if (lane == 0) red[warp] = s;
    __syncthreads();
    float ts = 0.0f;
    #pragma unroll
    for (int w = 0; w < 8; ++w) ts += red[w];

    float inv = 1.0f / ts;
    #pragma unroll
    for (int i = 0; i < 8; ++i)
        out[BATCH * BDIM + b * SEQ + i * 256 + tid] = vals[i] * inv;

    for (int d = tid; d < BDIM; d += 256) out[b * BDIM + d] = 0.0f;
}

// ---------------------------------------------------------------------------
// Kernel C: weighted_context[b,d] = sum_s attn[b,s] * X[b,s,d]
// 512 CTAs (16 s-chunks x 32 batches), 128 thr x 8 d's (one uint4/row),
// attn chunk staged in smem.
// ---------------------------------------------------------------------------
__global__ __launch_bounds__(128)
void weighted_kernel(float* __restrict__ out) {
    __shared__ float aw[128];
    const int b  = blockIdx.z;
    const int s0 = blockIdx.y * 128;
    const int d8 = threadIdx.x * 8;

    aw[threadIdx.x] = out[BATCH * BDIM + b * SEQ + s0 + threadIdx.x];
    __syncthreads();

    const __half* xb = g_Xh + ((size_t)b * SEQ + s0) * BDIM + d8;

    float acc[8] = {0.f, 0.f, 0.f, 0.f, 0.f, 0.f, 0.f, 0.f};
    #pragma unroll 4
    for (int s = 0; s < 128; ++s) {
        uint4 raw = *(const uint4*)(xb + (size_t)s * BDIM);
        const __half2* h = (const __half2*)&raw;
        float w = aw[s];
        #pragma unroll
        for (int q = 0; q < 4; ++q) {
            float2 x = __half22float2(h[q]);
            acc[2*q]     += w * x.x;
            acc[2*q + 1] += w * x.y;
        }
    }
    #pragma unroll
    for (int q = 0; q < 8; ++q)
        atomicAdd(&out[b * BDIM + d8 + q], acc[q]);
}

// ---------------------------------------------------------------------------
extern "C" void kernel_launch(void* const* d_in, const int* in_sizes, int n_in,
                              void* d_out, int out_size) {
    const float* X = (const float*)d_in[0];   // context [32,2048,1024]
    const float* W = (const float*)d_in[1];   // [1024,1024]
    const float* v = (const float*)d_in[2];   // [1024]
    float* out = (float*)d_out;               // [wc 32*1024 | attn 32*2048]

    cvt_all_kernel<<<XBLOCKS + WBLOCKS, 256>>>(X, W);
    noop_kernel<<<1, 32>>>();                 // ncu alignment: -s 5 -> logits
    noop_kernel<<<1, 32>>>();

    cudaFuncSetAttribute(logits_kernel,
                         cudaFuncAttributeMaxDynamicSharedMemorySize, SMEM_BYTES);
    logits_kernel<<<MROWS / BM, 256, SMEM_BYTES>>>(v);
    softmax_kernel<<<BATCH, 256>>>(out);
    weighted_kernel<<<dim3(1, 16, BATCH), 128>>>(out);
}